// round 2
// baseline (speedup 1.0000x reference)
#include <cuda_runtime.h>
#include <cuda_bf16.h>
#include <math.h>

// ---------------------------------------------------------------------------
// GraphSAGE (3-layer) on GB300.
//   L1: h1 = relu( mean_agg(x) @ W1l + x @ W1r + b1 )           [N,256]
//   L2: h2 = relu( mean_agg(h1 @ W2l) + h1 @ W2r + b2 )         [N,128]
//   L3: out = log_softmax( mean_agg(h2 @ W3l) + h2 @ W3r + b3 ) [N,64]
// mean commutes with the linear map, so L2/L3 project first and aggregate at
// the smaller output dim.
// edge_index dtype is detected on-device (int32 vs int64) and normalized.
// ---------------------------------------------------------------------------

#define N_NODES 100000
#define E_EDGES 600000

// ---- scratch (device globals: no allocation allowed) ----
__device__ float g_agg [N_NODES * 128];
__device__ float g_h1  [N_NODES * 256];
__device__ float g_p2l [N_NODES * 128];
__device__ float g_p2r [N_NODES * 128];
__device__ float g_h2  [N_NODES * 128];
__device__ float g_p3l [N_NODES * 64];
__device__ float g_p3r [N_NODES * 64];
__device__ int   g_rowptr[N_NODES + 1];
__device__ int   g_cnt   [N_NODES];      // histogram, then fill cursor
__device__ int   g_esrc  [E_EDGES];      // src ids sorted by dst (CSR)
__device__ int   g_edge  [2 * E_EDGES];  // normalized int32 [src | dst]
__device__ int   g_is64;

// ---------------------------------------------------------------------------
// Edge dtype detection + normalization
// ---------------------------------------------------------------------------
__global__ void detect_kernel(const int* __restrict__ buf) {
    if (blockIdx.x == 0 && threadIdx.x == 0) {
        int all0 = 1;
        for (int i = 0; i < 128; i++)
            if (buf[2 * i + 1] != 0) { all0 = 0; break; }
        g_is64 = all0;   // int64 little-endian => hi words all zero
    }
}

__global__ void convert_kernel(const int* __restrict__ buf, int e2) {
    int i = blockIdx.x * blockDim.x + threadIdx.x;
    if (i < e2) {
        int v = g_is64 ? buf[2 * i] : buf[i];
        v = min(max(v, 0), N_NODES - 1);   // safety clamp
        g_edge[i] = v;
    }
}

// ---------------------------------------------------------------------------
// CSR build
// ---------------------------------------------------------------------------
__global__ void zero_cnt_kernel(int n) {
    int i = blockIdx.x * blockDim.x + threadIdx.x;
    if (i < n) g_cnt[i] = 0;
}

__global__ void hist_kernel(int e) {
    int i = blockIdx.x * blockDim.x + threadIdx.x;
    if (i < e) atomicAdd(&g_cnt[g_edge[E_EDGES + i]], 1);
}

// single-block exclusive scan
__global__ void scan_kernel(int n) {
    const int T = 1024;
    __shared__ int sums[T];
    int tid = threadIdx.x;
    int chunk = (n + T - 1) / T;
    int beg = min(tid * chunk, n);
    int end = min(beg + chunk, n);
    int s = 0;
    for (int i = beg; i < end; i++) s += g_cnt[i];
    sums[tid] = s;
    __syncthreads();
    for (int off = 1; off < T; off <<= 1) {
        int t = (tid >= off) ? sums[tid - off] : 0;
        __syncthreads();
        sums[tid] += t;
        __syncthreads();
    }
    int run = sums[tid] - s;
    for (int i = beg; i < end; i++) { g_rowptr[i] = run; run += g_cnt[i]; }
    if (tid == T - 1) g_rowptr[n] = sums[T - 1];
}

__global__ void cursor_kernel(int n) {
    int i = blockIdx.x * blockDim.x + threadIdx.x;
    if (i < n) g_cnt[i] = g_rowptr[i];
}

__global__ void fill_kernel(int e) {
    int i = blockIdx.x * blockDim.x + threadIdx.x;
    if (i < e) {
        int d = g_edge[E_EDGES + i];
        int pos = atomicAdd(&g_cnt[d], 1);
        if (pos >= 0 && pos < E_EDGES) g_esrc[pos] = g_edge[i];
    }
}

// ---------------------------------------------------------------------------
// Aggregation kernels (one warp per node, vectorized lanes)
// ---------------------------------------------------------------------------
__global__ void agg_mean128_kernel(const float* __restrict__ X,
                                   float* __restrict__ out, int n) {
    int gid  = blockIdx.x * blockDim.x + threadIdx.x;
    int node = gid >> 5;
    int lane = gid & 31;
    if (node >= n) return;
    int s0 = g_rowptr[node], s1 = g_rowptr[node + 1];
    float4 acc = make_float4(0.f, 0.f, 0.f, 0.f);
    for (int j = s0; j < s1; j++) {
        int s = g_esrc[j];
        float4 v = ((const float4*)(X + (size_t)s * 128))[lane];
        acc.x += v.x; acc.y += v.y; acc.z += v.z; acc.w += v.w;
    }
    float inv = 1.0f / (float)max(s1 - s0, 1);
    acc.x *= inv; acc.y *= inv; acc.z *= inv; acc.w *= inv;
    ((float4*)(out + (size_t)node * 128))[lane] = acc;
}

__global__ void agg_add_relu128_kernel(const float* __restrict__ Pl,
                                       const float* __restrict__ Pr,
                                       float* __restrict__ out, int n) {
    int gid  = blockIdx.x * blockDim.x + threadIdx.x;
    int node = gid >> 5;
    int lane = gid & 31;
    if (node >= n) return;
    int s0 = g_rowptr[node], s1 = g_rowptr[node + 1];
    float4 acc = make_float4(0.f, 0.f, 0.f, 0.f);
    for (int j = s0; j < s1; j++) {
        int s = g_esrc[j];
        float4 v = ((const float4*)(Pl + (size_t)s * 128))[lane];
        acc.x += v.x; acc.y += v.y; acc.z += v.z; acc.w += v.w;
    }
    float inv = 1.0f / (float)max(s1 - s0, 1);
    float4 r = ((const float4*)(Pr + (size_t)node * 128))[lane];
    float4 o;
    o.x = fmaxf(acc.x * inv + r.x, 0.f);
    o.y = fmaxf(acc.y * inv + r.y, 0.f);
    o.z = fmaxf(acc.z * inv + r.z, 0.f);
    o.w = fmaxf(acc.w * inv + r.w, 0.f);
    ((float4*)(out + (size_t)node * 128))[lane] = o;
}

__global__ void agg_add_lsm64_kernel(const float* __restrict__ Pl,
                                     const float* __restrict__ Pr,
                                     float* __restrict__ out, int n) {
    int gid  = blockIdx.x * blockDim.x + threadIdx.x;
    int node = gid >> 5;
    int lane = gid & 31;
    if (node >= n) return;
    int s0 = g_rowptr[node], s1 = g_rowptr[node + 1];
    float2 acc = make_float2(0.f, 0.f);
    for (int j = s0; j < s1; j++) {
        int s = g_esrc[j];
        float2 v = ((const float2*)(Pl + (size_t)s * 64))[lane];
        acc.x += v.x; acc.y += v.y;
    }
    float inv = 1.0f / (float)max(s1 - s0, 1);
    float2 r = ((const float2*)(Pr + (size_t)node * 64))[lane];
    float2 v;
    v.x = acc.x * inv + r.x;
    v.y = acc.y * inv + r.y;
    float m = fmaxf(v.x, v.y);
    #pragma unroll
    for (int off = 16; off >= 1; off >>= 1)
        m = fmaxf(m, __shfl_xor_sync(0xFFFFFFFFu, m, off));
    float se = expf(v.x - m) + expf(v.y - m);
    #pragma unroll
    for (int off = 16; off >= 1; off >>= 1)
        se += __shfl_xor_sync(0xFFFFFFFFu, se, off);
    float lse = m + logf(se);
    float2 o; o.x = v.x - lse; o.y = v.y - lse;
    ((float2*)(out + (size_t)node * 64))[lane] = o;
}

// ---------------------------------------------------------------------------
// Tiled fp32 GEMM with dual split-K inputs:
//   C[M,N] = A0[M,K0] @ B0[K0,N] + A1[M,K1] @ B1[K1,N] (+bias)(+relu)
// ---------------------------------------------------------------------------
template <int BM, int BN, int BK, int TM, int TN>
__global__ __launch_bounds__((BM / TM) * (BN / TN))
void gemm_dual_kernel(const float* __restrict__ A0, const float* __restrict__ B0, int K0,
                      const float* __restrict__ A1, const float* __restrict__ B1, int K1,
                      const float* __restrict__ bias, float* __restrict__ C,
                      int M, int N, int relu) {
    constexpr int THREADS = (BM / TM) * (BN / TN);
    __shared__ float As[BK][BM];
    __shared__ float Bs[BK][BN];

    const int tid  = threadIdx.x;
    const int tcol = tid % (BN / TN);
    const int trow = tid / (BN / TN);
    const int row0 = blockIdx.y * BM;
    const int col0 = blockIdx.x * BN;

    float acc[TM][TN];
    #pragma unroll
    for (int i = 0; i < TM; i++)
        #pragma unroll
        for (int j = 0; j < TN; j++) acc[i][j] = 0.f;

    const int kt0 = K0 / BK;
    const int kt1 = K1 / BK;

    for (int kt = 0; kt < kt0 + kt1; kt++) {
        const float* A; const float* B; int kbase, K_;
        if (kt < kt0) { A = A0; B = B0; kbase = kt * BK;         K_ = K0; }
        else          { A = A1; B = B1; kbase = (kt - kt0) * BK; K_ = K1; }

        #pragma unroll
        for (int i4 = tid; i4 < BM * BK / 4; i4 += THREADS) {
            int m  = i4 / (BK / 4);
            int k4 = (i4 % (BK / 4)) * 4;
            int gm = row0 + m;
            float4 v = make_float4(0.f, 0.f, 0.f, 0.f);
            if (gm < M) v = *(const float4*)&A[(size_t)gm * K_ + kbase + k4];
            As[k4 + 0][m] = v.x;
            As[k4 + 1][m] = v.y;
            As[k4 + 2][m] = v.z;
            As[k4 + 3][m] = v.w;
        }
        #pragma unroll
        for (int i4 = tid; i4 < BK * BN / 4; i4 += THREADS) {
            int k  = i4 / (BN / 4);
            int n4 = (i4 % (BN / 4)) * 4;
            float4 v = *(const float4*)&B[(size_t)(kbase + k) * N + col0 + n4];
            *(float4*)&Bs[k][n4] = v;
        }
        __syncthreads();

        #pragma unroll
        for (int k = 0; k < BK; k++) {
            float a[TM], b[TN];
            #pragma unroll
            for (int i = 0; i < TM; i += 4) {
                float4 v = *(const float4*)&As[k][trow * TM + i];
                a[i] = v.x; a[i + 1] = v.y; a[i + 2] = v.z; a[i + 3] = v.w;
            }
            #pragma unroll
            for (int j = 0; j < TN; j += 4) {
                float4 v = *(const float4*)&Bs[k][tcol * TN + j];
                b[j] = v.x; b[j + 1] = v.y; b[j + 2] = v.z; b[j + 3] = v.w;
            }
            #pragma unroll
            for (int i = 0; i < TM; i++)
                #pragma unroll
                for (int j = 0; j < TN; j++)
                    acc[i][j] += a[i] * b[j];
        }
        __syncthreads();
    }

    #pragma unroll
    for (int i = 0; i < TM; i++) {
        int gm = row0 + trow * TM + i;
        if (gm >= M) continue;
        #pragma unroll
        for (int j = 0; j < TN; j += 4) {
            int gn = col0 + tcol * TN + j;
            float4 v;
            v.x = acc[i][j + 0]; v.y = acc[i][j + 1];
            v.z = acc[i][j + 2]; v.w = acc[i][j + 3];
            if (bias) {
                v.x += bias[gn + 0]; v.y += bias[gn + 1];
                v.z += bias[gn + 2]; v.w += bias[gn + 3];
            }
            if (relu) {
                v.x = fmaxf(v.x, 0.f); v.y = fmaxf(v.y, 0.f);
                v.z = fmaxf(v.z, 0.f); v.w = fmaxf(v.w, 0.f);
            }
            *(float4*)&C[(size_t)gm * N + gn] = v;
        }
    }
}

// ---------------------------------------------------------------------------
extern "C" void kernel_launch(void* const* d_in, const int* in_sizes, int n_in,
                              void* d_out, int out_size) {
    const float* x   = (const float*)d_in[0];
    const int*   ei  = (const int*)d_in[1];   // raw words; dtype detected on device
    const float* W1l = (const float*)d_in[2];
    const float* W1r = (const float*)d_in[3];
    const float* b1  = (const float*)d_in[4];
    const float* W2l = (const float*)d_in[5];
    const float* W2r = (const float*)d_in[6];
    const float* b2  = (const float*)d_in[7];
    const float* W3l = (const float*)d_in[8];
    const float* W3r = (const float*)d_in[9];
    const float* b3  = (const float*)d_in[10];
    float* out = (float*)d_out;

    const int N = N_NODES;
    const int E = E_EDGES;

    float *p_agg, *p_h1, *p_p2l, *p_p2r, *p_h2, *p_p3l, *p_p3r;
    cudaGetSymbolAddress((void**)&p_agg, g_agg);
    cudaGetSymbolAddress((void**)&p_h1,  g_h1);
    cudaGetSymbolAddress((void**)&p_p2l, g_p2l);
    cudaGetSymbolAddress((void**)&p_p2r, g_p2r);
    cudaGetSymbolAddress((void**)&p_h2,  g_h2);
    cudaGetSymbolAddress((void**)&p_p3l, g_p3l);
    cudaGetSymbolAddress((void**)&p_p3r, g_p3r);

    const int TB = 256;
    dim3 gN((N + TB - 1) / TB);
    dim3 gE((E + TB - 1) / TB);
    dim3 gE2((2 * E + TB - 1) / TB);
    dim3 gWarp(((size_t)N * 32 + TB - 1) / TB);

    // ---- edge normalization + CSR build ----
    detect_kernel<<<1, 1>>>(ei);
    convert_kernel<<<gE2, TB>>>(ei, 2 * E);
    zero_cnt_kernel<<<gN, TB>>>(N);
    hist_kernel<<<gE, TB>>>(E);
    scan_kernel<<<1, 1024>>>(N);
    cursor_kernel<<<gN, TB>>>(N);
    fill_kernel<<<gE, TB>>>(E);

    const int MB = 128;
    dim3 gemmGrid256(256 / 128, (N + MB - 1) / MB);
    dim3 gemmGrid128(128 / 128, (N + MB - 1) / MB);
    dim3 gemmGrid64 (64  / 64,  (N + MB - 1) / MB);

    // ---- Layer 1: agg(x) then fused dual GEMM ----
    agg_mean128_kernel<<<gWarp, TB>>>(x, p_agg, N);
    gemm_dual_kernel<128, 128, 8, 8, 8><<<gemmGrid256, 256>>>(
        p_agg, W1l, 128, x, W1r, 128, b1, p_h1, N, 256, 1);

    // ---- Layer 2: project first, aggregate at 128 ----
    gemm_dual_kernel<128, 128, 8, 8, 8><<<gemmGrid128, 256>>>(
        p_h1, W2l, 256, (const float*)0, (const float*)0, 0, (const float*)0,
        p_p2l, N, 128, 0);
    gemm_dual_kernel<128, 128, 8, 8, 8><<<gemmGrid128, 256>>>(
        p_h1, W2r, 256, (const float*)0, (const float*)0, 0, b2,
        p_p2r, N, 128, 0);
    agg_add_relu128_kernel<<<gWarp, TB>>>(p_p2l, p_p2r, p_h2, N);

    // ---- Layer 3: project first, aggregate at 64, fused log_softmax ----
    gemm_dual_kernel<128, 64, 8, 8, 4><<<gemmGrid64, 256>>>(
        p_h2, W3l, 128, (const float*)0, (const float*)0, 0, (const float*)0,
        p_p3l, N, 64, 0);
    gemm_dual_kernel<128, 64, 8, 8, 4><<<gemmGrid64, 256>>>(
        p_h2, W3r, 128, (const float*)0, (const float*)0, 0, b3,
        p_p3r, N, 64, 0);
    agg_add_lsm64_kernel<<<gWarp, TB>>>(p_p3l, p_p3r, out, N);
}